// round 1
// baseline (speedup 1.0000x reference)
#include <cuda_runtime.h>

#define B_TOTAL 32768
#define NNODES  16
#define NDIM    64
#define HID     128
#define NHEAD   4
#define HD      32
#define NLAYER  2
#define NC      10
#define G       4            // graphs per block
#define THREADS 256
#define SPAD    132          // padded row stride (floats) for h/Q/K/V
#define GSTRIDE (NNODES*SPAD)   // 2112 floats per graph slot

// shared memory layout (in floats)
#define OFF_W    0                       // 16384 floats (128x128 weight stage)
#define OFF_BIAS 16384                   // 256 floats (bias / ln params)
#define OFF_H    16640
#define OFF_Q    (OFF_H + G*GSTRIDE)     // 25088
#define OFF_K    (OFF_Q + G*GSTRIDE)     // 33536
#define OFF_V    (OFF_K + G*GSTRIDE)     // 41984
#define SMEM_FLOATS (OFF_V + G*GSTRIDE)  // 50432
#define SMEM_BYTES  (SMEM_FLOATS*4)      // 201728 bytes

typedef unsigned long long ull;

__device__ __forceinline__ ull pack2(float x, float y) {
    ull r; asm("mov.b64 %0, {%1,%2};" : "=l"(r) : "f"(x), "f"(y)); return r;
}
__device__ __forceinline__ float2 unpack2(ull v) {
    float2 r; asm("mov.b64 {%0,%1}, %2;" : "=f"(r.x), "=f"(r.y) : "l"(v)); return r;
}
__device__ __forceinline__ void fma2(ull& d, ull a, ull b) {
    asm("fma.rn.f32x2 %0, %1, %2, %0;" : "+l"(d) : "l"(a), "l"(b));
}

// block-cooperative global->shared copy (n need not be multiple of 4)
__device__ __forceinline__ void cp_smem(float* dst, const float* __restrict__ src,
                                        int n, int tid) {
    int n4 = n >> 2;
    for (int i = tid; i < n4; i += THREADS)
        ((float4*)dst)[i] = ((const float4*)src)[i];
    for (int i = (n4 << 2) + tid; i < n; i += THREADS)
        dst[i] = src[i];
}

// Warp GEMM: out[n0..n0+8][0..128) = in[n0..n0+8][0..K) @ Wsh[K][128] + bias
// lane owns 4 contiguous output columns; accumulators packed f32x2.
template<int K, int INSTRIDE>
__device__ __forceinline__ void gemm_warp(const float* __restrict__ in,
                                          const float* __restrict__ Wsh,
                                          const float* __restrict__ bias,
                                          float* __restrict__ out,
                                          int n0, int lane)
{
    const int c = lane << 2;
    const ull bA = pack2(bias[c],   bias[c+1]);
    const ull bB = pack2(bias[c+2], bias[c+3]);
    ull accA[8], accB[8];
#pragma unroll
    for (int n = 0; n < 8; n++) { accA[n] = bA; accB[n] = bB; }
#pragma unroll 2
    for (int k0 = 0; k0 < K; k0 += 4) {
        float4 w0 = *(const float4*)(Wsh + (k0    )*HID + c);
        float4 w1 = *(const float4*)(Wsh + (k0 + 1)*HID + c);
        float4 w2 = *(const float4*)(Wsh + (k0 + 2)*HID + c);
        float4 w3 = *(const float4*)(Wsh + (k0 + 3)*HID + c);
        ull w0A = pack2(w0.x, w0.y), w0B = pack2(w0.z, w0.w);
        ull w1A = pack2(w1.x, w1.y), w1B = pack2(w1.z, w1.w);
        ull w2A = pack2(w2.x, w2.y), w2B = pack2(w2.z, w2.w);
        ull w3A = pack2(w3.x, w3.y), w3B = pack2(w3.z, w3.w);
#pragma unroll
        for (int n = 0; n < 8; n++) {
            float4 hv = *(const float4*)(in + (n0 + n)*INSTRIDE + k0);
            ull h0 = pack2(hv.x, hv.x), h1 = pack2(hv.y, hv.y);
            ull h2 = pack2(hv.z, hv.z), h3 = pack2(hv.w, hv.w);
            fma2(accA[n], h0, w0A); fma2(accB[n], h0, w0B);
            fma2(accA[n], h1, w1A); fma2(accB[n], h1, w1B);
            fma2(accA[n], h2, w2A); fma2(accB[n], h2, w2B);
            fma2(accA[n], h3, w3A); fma2(accB[n], h3, w3B);
        }
    }
#pragma unroll
    for (int n = 0; n < 8; n++) {
        float2 a = unpack2(accA[n]), b = unpack2(accB[n]);
        *(float4*)(out + (n0 + n)*SPAD + c) = make_float4(a.x, a.y, b.x, b.y);
    }
}

__global__ void __launch_bounds__(THREADS, 1)
gnn_fused_kernel(const float* __restrict__ x,
                 const float* __restrict__ enc_W, const float* __restrict__ enc_b,
                 const float* __restrict__ Wq, const float* __restrict__ bq,
                 const float* __restrict__ Wk, const float* __restrict__ bk,
                 const float* __restrict__ Wv, const float* __restrict__ bv,
                 const float* __restrict__ ln_g, const float* __restrict__ ln_b,
                 const float* __restrict__ W1, const float* __restrict__ b1,
                 const float* __restrict__ W2, const float* __restrict__ b2,
                 float* __restrict__ out)
{
    extern __shared__ float sm[];
    float* Wsh  = sm + OFF_W;
    float* bias = sm + OFF_BIAS;

    const int tid  = threadIdx.x;
    const int lane = tid & 31;
    const int warp = tid >> 5;
    const int gs   = warp >> 1;   // graph slot 0..3
    const int wsub = warp & 1;    // sub-warp within graph
    const int n0   = wsub * 8;    // node range for GEMM

    float* hg = sm + OFF_H + gs*GSTRIDE;
    float* qg = sm + OFF_Q + gs*GSTRIDE;
    float* kg = sm + OFF_K + gs*GSTRIDE;
    float* vg = sm + OFF_V + gs*GSTRIDE;

    // ---- load x tile (4 graphs, 4096 contiguous floats) into Q region (stride 64) ----
    {
        const float4* xs = (const float4*)(x + (size_t)blockIdx.x * (G*NNODES*NDIM));
        float* xb = sm + OFF_Q;
        for (int i = tid; i < (G*NNODES*NDIM)/4; i += THREADS) {
            int g = i >> 8;      // 256 float4 per graph
            int r = i & 255;
            *(float4*)(xb + g*GSTRIDE + (r << 2)) = xs[i];
        }
    }
    cp_smem(Wsh,  enc_W, NDIM*HID, tid);
    cp_smem(bias, enc_b, HID,      tid);
    __syncthreads();

    // ---- encode: h = x @ enc_W + enc_b ----
    gemm_warp<NDIM, NDIM>(qg, Wsh, bias, hg, n0, lane);
    __syncthreads();

    const float scale = 0.1767766952966369f;   // 1/sqrt(32)

    for (int layer = 0; layer < NLAYER; layer++) {
        // Q
        cp_smem(Wsh,  Wq + layer*HID*HID, HID*HID, tid);
        cp_smem(bias, bq + layer*HID,     HID,     tid);
        __syncthreads();
        gemm_warp<HID, SPAD>(hg, Wsh, bias, qg, n0, lane);
        __syncthreads();
        // K
        cp_smem(Wsh,  Wk + layer*HID*HID, HID*HID, tid);
        cp_smem(bias, bk + layer*HID,     HID,     tid);
        __syncthreads();
        gemm_warp<HID, SPAD>(hg, Wsh, bias, kg, n0, lane);
        __syncthreads();
        // V
        cp_smem(Wsh,  Wv + layer*HID*HID, HID*HID, tid);
        cp_smem(bias, bv + layer*HID,     HID,     tid);
        __syncthreads();
        gemm_warp<HID, SPAD>(hg, Wsh, bias, vg, n0, lane);
        __syncthreads();
        // LN params into bias buffer
        cp_smem(bias,       ln_g + layer*HID, HID, tid);
        cp_smem(bias + HID, ln_b + layer*HID, HID, tid);
        __syncthreads();

        // ---- attention + residual + layernorm (fully in registers) ----
        {
            const int n  = n0 + (lane & 7);
            const int hh = lane >> 3;
            const int co = hh * HD;

            float q[32];
            const float* qr = qg + n*SPAD + co;
#pragma unroll
            for (int j = 0; j < 8; j++) {
                float4 t = *(const float4*)(qr + 4*j);
                q[4*j] = t.x; q[4*j+1] = t.y; q[4*j+2] = t.z; q[4*j+3] = t.w;
            }
            float s[16];
#pragma unroll
            for (int m = 0; m < 16; m++) {
                const float* kr = kg + m*SPAD + co;
                float a0 = 0.f, a1 = 0.f, a2 = 0.f, a3 = 0.f;
#pragma unroll
                for (int j = 0; j < 8; j++) {
                    float4 t = *(const float4*)(kr + 4*j);
                    a0 += q[4*j]  *t.x; a1 += q[4*j+1]*t.y;
                    a2 += q[4*j+2]*t.z; a3 += q[4*j+3]*t.w;
                }
                s[m] = (a0 + a1 + a2 + a3) * scale;
            }
            float mx = s[0];
#pragma unroll
            for (int m = 1; m < 16; m++) mx = fmaxf(mx, s[m]);
            float ssum = 0.f;
#pragma unroll
            for (int m = 0; m < 16; m++) { s[m] = __expf(s[m] - mx); ssum += s[m]; }
            float inv = 1.f / ssum;

            float o[32];
#pragma unroll
            for (int j = 0; j < 32; j++) o[j] = 0.f;
#pragma unroll
            for (int m = 0; m < 16; m++) {
                float p = s[m] * inv;
                const float* vr = vg + m*SPAD + co;
#pragma unroll
                for (int j = 0; j < 8; j++) {
                    float4 t = *(const float4*)(vr + 4*j);
                    o[4*j]   += p*t.x; o[4*j+1] += p*t.y;
                    o[4*j+2] += p*t.z; o[4*j+3] += p*t.w;
                }
            }
            // residual
            float* hr = hg + n*SPAD + co;
#pragma unroll
            for (int j = 0; j < 8; j++) {
                float4 t = *(const float4*)(hr + 4*j);
                o[4*j] += t.x; o[4*j+1] += t.y; o[4*j+2] += t.z; o[4*j+3] += t.w;
            }
            // LN stats across 4 head-lanes of the same node
            float lsum = 0.f, lsq = 0.f;
#pragma unroll
            for (int j = 0; j < 32; j++) { lsum += o[j]; lsq += o[j]*o[j]; }
            lsum += __shfl_xor_sync(0xffffffffu, lsum, 8);
            lsq  += __shfl_xor_sync(0xffffffffu, lsq,  8);
            lsum += __shfl_xor_sync(0xffffffffu, lsum, 16);
            lsq  += __shfl_xor_sync(0xffffffffu, lsq,  16);
            float mean = lsum * (1.f/HID);
            float var  = lsq  * (1.f/HID) - mean*mean;
            float rstd = rsqrtf(var + 1e-5f);
#pragma unroll
            for (int j = 0; j < 32; j++)
                o[j] = (o[j] - mean) * rstd * bias[co + j] + bias[HID + co + j];
#pragma unroll
            for (int j = 0; j < 8; j++)
                *(float4*)(hr + 4*j) = make_float4(o[4*j], o[4*j+1], o[4*j+2], o[4*j+3]);
        }
        __syncthreads();
    }

    // ---- pooling: pooled[0..128)=mean, [128..256)=max  (into Q region) ----
    {
        int cA = wsub*64 + lane;
        int cB = cA + 32;
        float sA = 0.f, sB = 0.f, mA = -3.4e38f, mB = -3.4e38f;
#pragma unroll
        for (int nn = 0; nn < 16; nn++) {
            float a = hg[nn*SPAD + cA]; sA += a; mA = fmaxf(mA, a);
            float b = hg[nn*SPAD + cB]; sB += b; mB = fmaxf(mB, b);
        }
        qg[cA]       = sA * (1.f/16.f);
        qg[HID + cA] = mA;
        qg[cB]       = sB * (1.f/16.f);
        qg[HID + cB] = mB;
    }
    __syncthreads();

    // ---- MLP: hid = relu(pooled @ W1 + b1) in two K-stages (W1 is 256x128) ----
    cp_smem(Wsh,  W1, HID*HID, tid);   // rows 0..127 (mean part)
    cp_smem(bias, b1, HID,     tid);
    __syncthreads();
    float acc1, acc2;
    {
        int cA = wsub*64 + lane;
        int cB = cA + 32;
        acc1 = bias[cA]; acc2 = bias[cB];
#pragma unroll 8
        for (int k = 0; k < HID; k++) {
            float pv = qg[k];
            acc1 += pv * Wsh[k*HID + cA];
            acc2 += pv * Wsh[k*HID + cB];
        }
    }
    __syncthreads();
    cp_smem(Wsh, W1 + HID*HID, HID*HID, tid);   // rows 128..255 (max part)
    __syncthreads();
    {
        int cA = wsub*64 + lane;
        int cB = cA + 32;
#pragma unroll 8
        for (int k = 0; k < HID; k++) {
            float pv = qg[HID + k];
            acc1 += pv * Wsh[k*HID + cA];
            acc2 += pv * Wsh[k*HID + cB];
        }
        kg[cA] = fmaxf(acc1, 0.f);
        kg[cB] = fmaxf(acc2, 0.f);
    }
    __syncthreads();

    // ---- logits = hid @ W2 + b2 ----
    cp_smem(Wsh,  W2, HID*NC, tid);
    cp_smem(bias, b2, NC,     tid);
    __syncthreads();
    if (wsub == 0 && lane < NC) {
        float a = bias[lane];
#pragma unroll 8
        for (int c2 = 0; c2 < HID; c2++)
            a += kg[c2] * Wsh[c2*NC + lane];
        out[(size_t)(blockIdx.x*G + gs)*NC + lane] = a;
    }
}

extern "C" void kernel_launch(void* const* d_in, const int* in_sizes, int n_in,
                              void* d_out, int out_size)
{
    const float* x     = (const float*)d_in[0];
    const float* enc_W = (const float*)d_in[1];
    const float* enc_b = (const float*)d_in[2];
    const float* Wq    = (const float*)d_in[3];
    const float* bq    = (const float*)d_in[4];
    const float* Wk    = (const float*)d_in[5];
    const float* bk    = (const float*)d_in[6];
    const float* Wv    = (const float*)d_in[7];
    const float* bv    = (const float*)d_in[8];
    const float* ln_g  = (const float*)d_in[9];
    const float* ln_b  = (const float*)d_in[10];
    const float* W1    = (const float*)d_in[11];
    const float* b1    = (const float*)d_in[12];
    const float* W2    = (const float*)d_in[13];
    const float* b2    = (const float*)d_in[14];
    float* out = (float*)d_out;

    cudaFuncSetAttribute(gnn_fused_kernel,
                         cudaFuncAttributeMaxDynamicSharedMemorySize, SMEM_BYTES);

    dim3 grid(B_TOTAL / G);
    dim3 block(THREADS);
    gnn_fused_kernel<<<grid, block, SMEM_BYTES>>>(
        x, enc_W, enc_b, Wq, bq, Wk, bk, Wv, bv, ln_g, ln_b, W1, b1, W2, b2, out);
}

// round 4
// speedup vs baseline: 1.1842x; 1.1842x over previous
#include <cuda_runtime.h>

#define B_TOTAL 32768
#define NNODES  16
#define NDIM    64
#define HID     128
#define NC      10
#define G       4
#define THREADS 256
#define SPAD    132                 // h/Q/K/V row stride (floats), as in R1
#define GSTRIDE (NNODES*SPAD)       // 2112 floats per buffer per graph

// shared memory layout (float offsets)
#define OFF_WB0   0                 // 8192 fl = 32KB weight chunk buffer 0
#define OFF_WB1   8192              // buffer 1
#define OFF_BIAS  16384
#define   B_ENC   0
#define   B_BQ    128               // +128*l
#define   B_BK    384
#define   B_BV    640
#define   B_LNG   896
#define   B_LNB   1152
#define   B_B1    1408
#define   B_B2    1536
#define OFF_DATA  18048
#define GFL       (4*GSTRIDE)       // per-graph: h | q | k | v  = 8448
#define SMEM_FLOATS (OFF_DATA + G*GFL)      // 51840
#define SMEM_BYTES  (SMEM_FLOATS*4)         // 207360

typedef unsigned long long ull;

__device__ __forceinline__ ull pack2(float x, float y) {
    ull r; asm("mov.b64 %0, {%1,%2};" : "=l"(r) : "f"(x), "f"(y)); return r;
}
__device__ __forceinline__ float2 unpack2(ull v) {
    float2 r; asm("mov.b64 {%0,%1}, %2;" : "=f"(r.x), "=f"(r.y) : "l"(v)); return r;
}
__device__ __forceinline__ void fma2(ull& d, ull a, ull b) {
    asm("fma.rn.f32x2 %0, %1, %2, %0;" : "+l"(d) : "l"(a), "l"(b));
}
__device__ __forceinline__ unsigned su32(const void* p) {
    return (unsigned)__cvta_generic_to_shared(p);
}

// issue one weight chunk: all 256 threads copy 16B vectors, one commit_group
__device__ __forceinline__ void issue_chunk(float* dst, const float* __restrict__ src,
                                            int tid, int nvec) {
    unsigned d = su32(dst);
    for (int i = tid; i < nvec; i += THREADS)
        asm volatile("cp.async.cg.shared.global [%0], [%1], 16;"
                     :: "r"(d + 16u*(unsigned)i), "l"(src + 4*i) : "memory");
    asm volatile("cp.async.commit_group;" ::: "memory");
}
#define CHUNK_WAIT1() do { asm volatile("cp.async.wait_group 1;" ::: "memory"); \
                           __syncthreads(); } while (0)
#define CHUNK_WAIT0() do { asm volatile("cp.async.wait_group 0;" ::: "memory"); \
                           __syncthreads(); } while (0)

// R1 gemm inner loop over a 64-row weight chunk.
// in: already offset to this warp's first node row (and k-base).
// Lane owns 4 contiguous output columns c..c+3; accA = (c,c+1), accB = (c+2,c+3).
template<int INSTRIDE>
__device__ __forceinline__ void gemm64(const float* __restrict__ in,
                                       const float* __restrict__ Wc,
                                       int c, ull* accA, ull* accB)
{
#pragma unroll 2
    for (int k0 = 0; k0 < 64; k0 += 4) {
        float4 w0 = *(const float4*)(Wc + (k0    )*HID + c);
        float4 w1 = *(const float4*)(Wc + (k0 + 1)*HID + c);
        float4 w2 = *(const float4*)(Wc + (k0 + 2)*HID + c);
        float4 w3 = *(const float4*)(Wc + (k0 + 3)*HID + c);
        ull w0A = pack2(w0.x, w0.y), w0B = pack2(w0.z, w0.w);
        ull w1A = pack2(w1.x, w1.y), w1B = pack2(w1.z, w1.w);
        ull w2A = pack2(w2.x, w2.y), w2B = pack2(w2.z, w2.w);
        ull w3A = pack2(w3.x, w3.y), w3B = pack2(w3.z, w3.w);
#pragma unroll
        for (int n = 0; n < 8; n++) {
            float4 hv = *(const float4*)(in + n*INSTRIDE + k0);
            ull h0 = pack2(hv.x, hv.x), h1 = pack2(hv.y, hv.y);
            ull h2 = pack2(hv.z, hv.z), h3 = pack2(hv.w, hv.w);
            fma2(accA[n], h0, w0A); fma2(accB[n], h0, w0B);
            fma2(accA[n], h1, w1A); fma2(accB[n], h1, w1B);
            fma2(accA[n], h2, w2A); fma2(accB[n], h2, w2B);
            fma2(accA[n], h3, w3A); fma2(accB[n], h3, w3B);
        }
    }
}

__device__ __forceinline__ void store_acc(float* __restrict__ out, int n0, int c,
                                          const ull* accA, const ull* accB)
{
#pragma unroll
    for (int n = 0; n < 8; n++) {
        float2 a = unpack2(accA[n]), b = unpack2(accB[n]);
        *(float4*)(out + (n0 + n)*SPAD + c) = make_float4(a.x, a.y, b.x, b.y);
    }
}

__global__ void __launch_bounds__(THREADS, 1)
gnn_fused_kernel(const float* __restrict__ x,
                 const float* __restrict__ enc_W, const float* __restrict__ enc_b,
                 const float* __restrict__ Wq, const float* __restrict__ bq,
                 const float* __restrict__ Wk, const float* __restrict__ bk,
                 const float* __restrict__ Wv, const float* __restrict__ bv,
                 const float* __restrict__ ln_g, const float* __restrict__ ln_b,
                 const float* __restrict__ W1, const float* __restrict__ b1,
                 const float* __restrict__ W2, const float* __restrict__ b2,
                 float* __restrict__ out)
{
    extern __shared__ float sm[];
    float* bias = sm + OFF_BIAS;

    const int tid  = threadIdx.x;
    const int lane = tid & 31;
    const int warp = tid >> 5;
    const int gs   = warp >> 1;
    const int wsub = warp & 1;
    const int n0   = wsub * 8;
    const int c    = lane << 2;       // my 4 output columns

    float* hg = sm + OFF_DATA + gs*GFL;
    float* qg = hg + GSTRIDE;
    float* kg = hg + 2*GSTRIDE;
    float* vg = hg + 3*GSTRIDE;

    // ---- first two weight chunks (groups 0, 1) ----
    issue_chunk(sm + OFF_WB0, enc_W, tid, 2048);   // c0: enc_W (64x128 whole)
    issue_chunk(sm + OFF_WB1, Wq,    tid, 2048);   // c1: Wq[0] rows 0..63

    // ---- preload biases / ln params ----
    for (int i = tid; i < 128; i += THREADS) {
        bias[B_ENC + i] = enc_b[i];
        bias[B_B1  + i] = b1[i];
    }
    for (int i = tid; i < 256; i += THREADS) {
        bias[B_BQ  + i] = bq[i];
        bias[B_BK  + i] = bk[i];
        bias[B_BV  + i] = bv[i];
        bias[B_LNG + i] = ln_g[i];
        bias[B_LNB + i] = ln_b[i];
    }
    if (tid < NC) bias[B_B2 + tid] = b2[tid];

    // ---- stage x (4 graphs x 1024 floats) into Q region, row stride 64 ----
    {
        const float4* xs = (const float4*)(x + (size_t)blockIdx.x * (G*NNODES*NDIM));
        float* xb = sm + OFF_DATA + GSTRIDE;     // qg of graph 0
        for (int i = tid; i < (G*NNODES*NDIM)/4; i += THREADS) {
            int g = i >> 8;              // 256 float4 per graph
            int r = i & 255;
            *(float4*)(xb + g*GFL + (r << 2)) = xs[i];
        }
    }

    int wc = 0;

    // ---- encode: h = x @ enc_W + enc_b  (K=64, one chunk) ----
    {
        CHUNK_WAIT1();     // c0 ready; biases + x staging published
        ull accA[8], accB[8];
        ull bA = pack2(bias[B_ENC + c],     bias[B_ENC + c + 1]);
        ull bB = pack2(bias[B_ENC + c + 2], bias[B_ENC + c + 3]);
#pragma unroll
        for (int n = 0; n < 8; n++) { accA[n] = bA; accB[n] = bB; }
        gemm64<NDIM>(qg + n0*NDIM, sm + OFF_WB0, c, accA, accB);
        store_acc(hg, n0, c, accA, accB);
        __syncthreads();
        issue_chunk(sm + OFF_WB0, Wq + 8192, tid, 2048);   // c2: Wq[0] rows 64..127
        wc = 1;
    }

    const float scale = 0.1767766952966369f;   // 1/sqrt(32)

    for (int l = 0; l < 2; l++) {
        // three projection stages; each consumes 2 chunks, prefetches 2
        const float* nexts[6] = {
            Wk + l*16384, Wk + l*16384 + 8192,
            Wv + l*16384, Wv + l*16384 + 8192,
            (l == 0) ? (Wq + 16384) : W1,
            (l == 0) ? (Wq + 16384 + 8192) : (W1 + 8192)
        };
        const float* bptr[3] = { bias + B_BQ + 128*l, bias + B_BK + 128*l,
                                 bias + B_BV + 128*l };
        float* outs[3] = { qg, kg, vg };

#pragma unroll
        for (int s = 0; s < 3; s++) {
            CHUNK_WAIT1();
            ull accA[8], accB[8];
            ull bA = pack2(bptr[s][c],     bptr[s][c + 1]);
            ull bB = pack2(bptr[s][c + 2], bptr[s][c + 3]);
#pragma unroll
            for (int n = 0; n < 8; n++) { accA[n] = bA; accB[n] = bB; }
            float* buf0 = sm + ((wc & 1) ? OFF_WB1 : OFF_WB0);
            gemm64<SPAD>(hg + n0*SPAD, buf0, c, accA, accB);
            __syncthreads();
            issue_chunk(buf0, nexts[2*s], tid, 2048);
            wc++;
            CHUNK_WAIT1();
            float* buf1 = sm + ((wc & 1) ? OFF_WB1 : OFF_WB0);
            gemm64<SPAD>(hg + n0*SPAD + 64, buf1, c, accA, accB);
            store_acc(outs[s], n0, c, accA, accB);
            __syncthreads();
            issue_chunk(buf1, nexts[2*s + 1], tid, 2048);
            wc++;
        }

        // ---- attention + residual + layernorm (registers; lane=(node,head)) ----
        {
            const int n  = n0 + (lane & 7);
            const int hh = lane >> 3;
            const int co = hh * 32;

            float q[32];
            const float* qr = qg + n*SPAD + co;
#pragma unroll
            for (int j = 0; j < 8; j++) {
                float4 t = *(const float4*)(qr + 4*j);
                q[4*j] = t.x; q[4*j+1] = t.y; q[4*j+2] = t.z; q[4*j+3] = t.w;
            }
            float s[16];
#pragma unroll
            for (int m = 0; m < 16; m++) {
                const float* kr = kg + m*SPAD + co;
                float a0 = 0.f, a1 = 0.f, a2 = 0.f, a3 = 0.f;
#pragma unroll
                for (int j = 0; j < 8; j++) {
                    float4 t = *(const float4*)(kr + 4*j);
                    a0 += q[4*j]  *t.x; a1 += q[4*j+1]*t.y;
                    a2 += q[4*j+2]*t.z; a3 += q[4*j+3]*t.w;
                }
                s[m] = (a0 + a1 + a2 + a3) * scale;
            }
            float mx = s[0];
#pragma unroll
            for (int m = 1; m < 16; m++) mx = fmaxf(mx, s[m]);
            float ssum = 0.f;
#pragma unroll
            for (int m = 0; m < 16; m++) { s[m] = __expf(s[m] - mx); ssum += s[m]; }
            float inv = 1.f / ssum;

            float o[32];
#pragma unroll
            for (int j = 0; j < 32; j++) o[j] = 0.f;
#pragma unroll
            for (int m = 0; m < 16; m++) {
                float p = s[m] * inv;
                const float* vr = vg + m*SPAD + co;
#pragma unroll
                for (int j = 0; j < 8; j++) {
                    float4 t = *(const float4*)(vr + 4*j);
                    o[4*j]   += p*t.x; o[4*j+1] += p*t.y;
                    o[4*j+2] += p*t.z; o[4*j+3] += p*t.w;
                }
            }
            // residual
            float* hr = hg + n*SPAD + co;
#pragma unroll
            for (int j = 0; j < 8; j++) {
                float4 t = *(const float4*)(hr + 4*j);
                o[4*j] += t.x; o[4*j+1] += t.y; o[4*j+2] += t.z; o[4*j+3] += t.w;
            }
            // LN stats across the 4 head-lanes of this node
            float lsum = 0.f, lsq = 0.f;
#pragma unroll
            for (int j = 0; j < 32; j++) { lsum += o[j]; lsq += o[j]*o[j]; }
            lsum += __shfl_xor_sync(0xffffffffu, lsum, 8);
            lsq  += __shfl_xor_sync(0xffffffffu, lsq,  8);
            lsum += __shfl_xor_sync(0xffffffffu, lsum, 16);
            lsq  += __shfl_xor_sync(0xffffffffu, lsq,  16);
            float mean = lsum * (1.f/HID);
            float var  = lsq  * (1.f/HID) - mean*mean;
            float rstd = rsqrtf(var + 1e-5f);
#pragma unroll
            for (int j = 0; j < 32; j++)
                o[j] = (o[j] - mean) * rstd * bias[B_LNG + 128*l + co + j]
                       + bias[B_LNB + 128*l + co + j];
#pragma unroll
            for (int j = 0; j < 8; j++)
                *(float4*)(hr + 4*j) = make_float4(o[4*j], o[4*j+1], o[4*j+2], o[4*j+3]);
        }
        __syncthreads();
    }

    // ---- pooling into qg: [0..128)=mean, [128..256)=max ----
    {
        int cA = wsub*64 + lane, cB = cA + 32;
        float sA = 0.f, sB = 0.f, mA = -3.4e38f, mB = -3.4e38f;
#pragma unroll
        for (int nn = 0; nn < 16; nn++) {
            float a = hg[nn*SPAD + cA]; sA += a; mA = fmaxf(mA, a);
            float b = hg[nn*SPAD + cB]; sB += b; mB = fmaxf(mB, b);
        }
        qg[cA]       = sA * (1.f/16.f);
        qg[HID + cA] = mA;
        qg[cB]       = sB * (1.f/16.f);
        qg[HID + cB] = mB;
    }
    __syncthreads();

    // ---- MLP layer 1: 4 chunks of W1 (256x128); c13,c14 already in flight ----
    {
        int cA = wsub*64 + lane, cB = cA + 32;
        float a1 = bias[B_B1 + cA];
        float a2 = bias[B_B1 + cB];
        for (int cc = 0; cc < 4; cc++) {
            CHUNK_WAIT1();
            float* bufp = sm + ((wc & 1) ? OFF_WB1 : OFF_WB0);
#pragma unroll 8
            for (int k = 0; k < 64; k++) {
                float pv = qg[64*cc + k];
                a1 = fmaf(pv, bufp[k*HID + cA], a1);
                a2 = fmaf(pv, bufp[k*HID + cB], a2);
            }
            __syncthreads();
            if (cc < 3) {
                const float* src = (cc < 2) ? (W1 + (cc + 2)*8192) : W2;
                int nv = (cc < 2) ? 2048 : 320;    // W2 = 128*10 floats = 5120 B
                issue_chunk(bufp, src, tid, nv);
            }
            wc++;
        }
        kg[cA] = fmaxf(a1, 0.f);
        kg[cB] = fmaxf(a2, 0.f);
    }
    __syncthreads();

    // ---- logits = hid @ W2 + b2 ----
    CHUNK_WAIT0();
    {
        const float* Wc = sm + ((wc & 1) ? OFF_WB1 : OFF_WB0);
        if (wsub == 0 && lane < NC) {
            float a = bias[B_B2 + lane];
#pragma unroll 8
            for (int k = 0; k < HID; k++)
                a = fmaf(kg[k], Wc[k*NC + lane], a);
            out[((size_t)blockIdx.x*G + gs)*NC + lane] = a;
        }
    }
}

extern "C" void kernel_launch(void* const* d_in, const int* in_sizes, int n_in,
                              void* d_out, int out_size)
{
    const float* x     = (const float*)d_in[0];
    const float* enc_W = (const float*)d_in[1];
    const float* enc_b = (const float*)d_in[2];
    const float* Wq    = (const float*)d_in[3];
    const float* bq    = (const float*)d_in[4];
    const float* Wk    = (const float*)d_in[5];
    const float* bk    = (const float*)d_in[6];
    const float* Wv    = (const float*)d_in[7];
    const float* bv    = (const float*)d_in[8];
    const float* ln_g  = (const float*)d_in[9];
    const float* ln_b  = (const float*)d_in[10];
    const float* W1    = (const float*)d_in[11];
    const float* b1    = (const float*)d_in[12];
    const float* W2    = (const float*)d_in[13];
    const float* b2    = (const float*)d_in[14];
    float* out = (float*)d_out;

    cudaFuncSetAttribute(gnn_fused_kernel,
                         cudaFuncAttributeMaxDynamicSharedMemorySize, SMEM_BYTES);

    gnn_fused_kernel<<<B_TOTAL / G, THREADS, SMEM_BYTES>>>(
        x, enc_W, enc_b, Wq, bq, Wk, bk, Wv, bv, ln_g, ln_b, W1, b1, W2, b2, out);
}